// round 14
// baseline (speedup 1.0000x reference)
#include <cuda_runtime.h>
#include <cuda_bf16.h>
#include <cuda_fp16.h>
#include <cstdint>

#define Bc 2
#define Cc 512
#define NHc 8
#define NPc 4
#define HDc 64
#define Dim 20
#define Nspat 8000          // 20*20*20
#define MTOT (Bc*Nspat)     // 16000
#define LN_EPS 1e-5f

// ---------------- scratch ----------------
__device__ __align__(16) __half g_q   [(size_t)MTOT*Cc];
__device__ __align__(16) __half g_hid [(size_t)MTOT*Cc];
__device__ __align__(16) __half g_s   [(size_t)MTOT*Cc];
__device__ __align__(16) float g_off [(size_t)MTOT*NHc*NPc*3];
__device__ __align__(16) float g_attn[(size_t)MTOT*NHc*NPc];
__device__ __align__(16) __half g_feats[(size_t)Bc*NHc*Nspat*HDc];
__device__ __align__(256) __half g_W1  [640*512];   // folded [Wo1T;WaT]@Wq
__device__ __align__(256) __half g_Wo2 [128*512];
__device__ __align__(256) __half g_Wout[512*512];
__device__ float g_bc[640];

// ================= helpers =================
__device__ __forceinline__ uint32_t smem_u32(const void* p) {
    uint32_t a;
    asm("{ .reg .u64 t; cvta.to.shared.u64 t, %1; cvt.u32.u64 %0, t; }" : "=r"(a) : "l"(p));
    return a;
}
__device__ __forceinline__ void ldsm4(uint32_t* r, uint32_t addr) {
    asm volatile("ldmatrix.sync.aligned.m8n8.x4.shared.b16 {%0,%1,%2,%3}, [%4];"
        : "=r"(r[0]), "=r"(r[1]), "=r"(r[2]), "=r"(r[3]) : "r"(addr));
}
__device__ __forceinline__ void mma_f16(float* c, const uint32_t* a, const uint32_t* b) {
    asm volatile(
        "mma.sync.aligned.m16n8k16.row.col.f32.f16.f16.f32 "
        "{%0,%1,%2,%3}, {%4,%5,%6,%7}, {%8,%9}, {%0,%1,%2,%3};"
        : "+f"(c[0]), "+f"(c[1]), "+f"(c[2]), "+f"(c[3])
        : "r"(a[0]), "r"(a[1]), "r"(a[2]), "r"(a[3]), "r"(b[0]), "r"(b[1]));
}
#define CPA16(dst, src) \
    asm volatile("cp.async.cg.shared.global [%0], [%1], 16;" :: "r"(dst), "l"(src) : "memory")

// ================= fp16 HMMA GEMM (single-A, BK=64, 3-stage, 1 barrier/iter) =================
// Tile 128x128. Stage: A(128x144B)@0, B@18432; stage=36864B. 3 stages = 110592B.
#define GM_STAGE 36864
#define GM_BOFF  18432
#define NS_SMEM  (3*GM_STAGE)   // 110592; also covers TR epilogue (66048)

// omode: 0 = fp32 row-major (+act 2 clip), 1 = fp32 transposed staged, 2 = relu -> fp16
__device__ __forceinline__ void sgemm_body(
    const __half* __restrict__ AH,
    const __half* __restrict__ Bs,
    const float* __restrict__ bias,
    float* __restrict__ Cf, __half* __restrict__ CH,
    int Nc, int act, int omode, int m0, int n0, char* sm)
{
    const uint32_t smb = smem_u32(sm);
    const int tid = threadIdx.x;
    const int wid = tid >> 5, lane = tid & 31;
    const int wm = wid >> 1;
    const int wn = wid & 1;

    const int tq = lane >> 3, rr = lane & 7;
    const int a_row = rr + (tq & 1) * 8;
    const int a_col = (tq >> 1) * 8;
    const int b_row = rr + (tq >> 1) * 8;
    const int b_col = (tq & 1) * 8;

    const int r2  = tid >> 1;            // 0..127
    const int kh2 = (tid & 1) * 32;      // half offset within row: 0 or 32

    const __half* AHp = AH + (size_t)(m0 + r2) * 512 + kh2;
    const __half* Bp  = Bs + (size_t)(n0 + r2) * 512 + kh2;

    auto ldAB = [&](int buf, int kt) {
        uint32_t ro = smb + buf * GM_STAGE + r2 * 144 + kh2 * 2;
        const int go = kt * 64;
        CPA16(ro,      AHp + go);
        CPA16(ro + 16, AHp + go + 8);
        CPA16(ro + 32, AHp + go + 16);
        CPA16(ro + 48, AHp + go + 24);
        CPA16(ro + GM_BOFF,      Bp + go);
        CPA16(ro + GM_BOFF + 16, Bp + go + 8);
        CPA16(ro + GM_BOFF + 32, Bp + go + 16);
        CPA16(ro + GM_BOFF + 48, Bp + go + 24);
        asm volatile("cp.async.commit_group;" ::: "memory");
    };

    float acc[2][8][4];
    #pragma unroll
    for (int mi = 0; mi < 2; ++mi)
        #pragma unroll
        for (int j = 0; j < 8; ++j)
            #pragma unroll
            for (int q = 0; q < 4; ++q) acc[mi][j][q] = 0.f;

    ldAB(0, 0);
    ldAB(1, 1);

    for (int kt = 0; kt < 8; ++kt) {
        if (kt < 7) {
            asm volatile("cp.async.wait_group 1;" ::: "memory");
        } else {
            asm volatile("cp.async.wait_group 0;" ::: "memory");
        }
        __syncthreads();    // stage kt visible; all warps done reading stage kt-1
        if (kt + 2 < 8)
            ldAB((kt + 2) % 3, kt + 2);   // overwrites buffer consumed at kt-1: safe after barrier
        uint32_t abase = smb + (kt % 3) * GM_STAGE;
        uint32_t bbase = abase + GM_BOFF;
        #pragma unroll
        for (int ks = 0; ks < 4; ++ks) {
            int kc = ks * 16;
            uint32_t ah[2][4], bf[4][4];
            #pragma unroll
            for (int mi = 0; mi < 2; ++mi) {
                uint32_t ad = abase + (uint32_t)(wm * 32 + mi * 16 + a_row) * 144 + (kc + a_col) * 2;
                ldsm4(ah[mi], ad);
            }
            #pragma unroll
            for (int p = 0; p < 4; ++p) {
                uint32_t bd = bbase + (uint32_t)(wn * 64 + p * 16 + b_row) * 144 + (kc + b_col) * 2;
                ldsm4(bf[p], bd);
            }
            #pragma unroll
            for (int mi = 0; mi < 2; ++mi)
                #pragma unroll
                for (int j = 0; j < 8; ++j)
                    mma_f16(acc[mi][j], ah[mi], &bf[j >> 1][(j & 1) * 2]);
        }
    }
    __syncthreads();

    if (omode == 1) {
        float* smf = (float*)sm;   // [128][129]
        #pragma unroll
        for (int mi = 0; mi < 2; ++mi) {
            #pragma unroll
            for (int j = 0; j < 8; ++j) {
                int c0 = wn * 64 + j * 8 + (lane & 3) * 2;
                float b0 = bias[n0 + c0], b1 = bias[n0 + c0 + 1];
                #pragma unroll
                for (int half = 0; half < 2; ++half) {
                    int r = wm * 32 + mi * 16 + (lane >> 2) + half * 8;
                    smf[r * 129 + c0]     = acc[mi][j][half * 2 + 0] + b0;
                    smf[r * 129 + c0 + 1] = acc[mi][j][half * 2 + 1] + b1;
                }
            }
        }
        __syncthreads();
        #pragma unroll 4
        for (int i = 0; i < 64; ++i) {
            int idx = i * 256 + tid;
            int cl = idx >> 7, rl = idx & 127;
            int row = m0 + rl;
            int b = row / Nspat, n = row - b * Nspat;
            Cf[((size_t)(b * Cc + n0 + cl)) * Nspat + n] = smf[rl * 129 + cl];
        }
        return;
    }

    #pragma unroll
    for (int mi = 0; mi < 2; ++mi) {
        int row0 = m0 + wm * 32 + mi * 16 + (lane >> 2);
        #pragma unroll
        for (int j = 0; j < 8; ++j) {
            int col0 = n0 + wn * 64 + j * 8 + (lane & 3) * 2;
            if (col0 >= Nc) continue;
            float b0 = bias[col0], b1 = bias[col0 + 1];
            #pragma unroll
            for (int half = 0; half < 2; ++half) {
                int row = row0 + half * 8;
                float v0 = acc[mi][j][half * 2 + 0] + b0;
                float v1 = acc[mi][j][half * 2 + 1] + b1;
                if (omode == 2) {
                    v0 = fmaxf(v0, 0.f); v1 = fmaxf(v1, 0.f);
                    *(__half2*)(CH + (size_t)row * Nc + col0) = __floats2half2_rn(v0, v1);
                } else {
                    if (act == 2) {
                        v0 = fminf(fmaxf(v0, -3.f), 3.f);
                        v1 = fminf(fmaxf(v1, -3.f), 3.f);
                    }
                    *(float2*)(Cf + (size_t)row * Nc + col0) = make_float2(v0, v1);
                }
            }
        }
    }
}

template<int ACT, int OMODE>
__global__ void __launch_bounds__(256, 2) k_sgemm(
    const __half* __restrict__ AH,
    const __half* __restrict__ Bs,
    const float* __restrict__ bias,
    float* __restrict__ Cf, __half* __restrict__ CH,
    int Nc)
{
    extern __shared__ __align__(1024) char sm_dyn[];
    sgemm_body(AH, Bs, bias, Cf, CH, Nc, ACT, OMODE,
               blockIdx.y * 128, blockIdx.x * 128, sm_dyn);
}

// dual: blocks [0,125) -> off = clip(hid@Wo2+bo2); [125,250) -> attn = q@W1[512:]+bc[512:]
__global__ void __launch_bounds__(256, 2) k_sgemm_dual(
    const __half* __restrict__ hid, const __half* __restrict__ wo2, const float* __restrict__ bo2,
    float* __restrict__ off,
    const __half* __restrict__ q, const __half* __restrict__ w1a, const float* __restrict__ bca,
    float* __restrict__ attn)
{
    extern __shared__ __align__(1024) char sm_dyn[];
    int by = blockIdx.y;
    if (by < 125)
        sgemm_body(hid, wo2, bo2, off, nullptr, NHc * NPc * 3, 2, 0, by * 128, 0, sm_dyn);
    else
        sgemm_body(q, w1a, bca, attn, nullptr, NHc * NPc, 0, 0, (by - 125) * 128, 0, sm_dyn);
}

// ---------------- merged prep ----------------
__global__ void k_prep(const float* __restrict__ Wout, const float* __restrict__ Wo2,
                       const float* __restrict__ Wo1,  const float* __restrict__ Wa,
                       const float* __restrict__ Wq,
                       const float* __restrict__ bq,   const float* __restrict__ bo1,
                       const float* __restrict__ ba) {
    __shared__ float T1[32][33];
    __shared__ float T2[32][33];
    int z = blockIdx.z;
    int tx = threadIdx.x, ty = threadIdx.y;
    if (z < 2) {
        const float* W = (z == 0) ? Wout : Wo2;
        __half* Hd = (z == 0) ? g_Wout : g_Wo2;
        int Ncols = (z == 0) ? 512 : NHc * NPc * 3;
        int Npad  = (z == 0) ? 512 : 128;
        int k0 = blockIdx.y * 32, n0 = blockIdx.x * 32;
        if (n0 >= Npad) return;
        #pragma unroll
        for (int i = 0; i < 32; i += 8) {
            int k = k0 + ty + i, n = n0 + tx;
            T1[ty + i][tx] = (n < Ncols) ? W[(size_t)k * Ncols + n] : 0.f;
        }
        __syncthreads();
        #pragma unroll
        for (int i = 0; i < 32; i += 8) {
            int n = n0 + ty + i, k = k0 + tx;
            Hd[(size_t)n * 512 + k] = __float2half_rn(T1[tx][ty + i]);
        }
        return;
    }
    if (z < 22) {
        if (blockIdx.y != 0) return;
        int n0 = (z - 2) * 32, j0 = blockIdx.x * 32;
        float acc[4] = {0.f, 0.f, 0.f, 0.f};
        for (int k0 = 0; k0 < 512; k0 += 32) {
            #pragma unroll
            for (int i = 0; i < 32; i += 8) {
                int k = k0 + ty + i, n = n0 + tx;
                float v = 0.f;
                if (n < 512)      v = Wo1[(size_t)k * 512 + n];
                else if (n < 544) v = Wa[(size_t)k * 32 + (n - 512)];
                T1[ty + i][tx] = v;
                T2[ty + i][tx] = Wq[(size_t)(j0 + ty + i) * 512 + k0 + tx];
            }
            __syncthreads();
            #pragma unroll 8
            for (int k = 0; k < 32; ++k) {
                float t1 = T1[k][tx];
                #pragma unroll
                for (int r = 0; r < 4; ++r) acc[r] += t1 * T2[ty + 8 * r][k];
            }
            __syncthreads();
        }
        #pragma unroll
        for (int r = 0; r < 4; ++r)
            g_W1[(size_t)(n0 + tx) * 512 + j0 + ty + 8 * r] = __float2half_rn(acc[r]);
        return;
    }
    if (blockIdx.y != 0 || blockIdx.x >= 3) return;
    int n = blockIdx.x * 256 + ty * 32 + tx;
    if (n >= 640) return;
    float s = 0.f;
    if (n < 512) {
        s = bo1[n];
        for (int j = 0; j < 512; ++j) s += bq[j] * Wo1[(size_t)j * 512 + n];
    } else if (n < 544) {
        int c = n - 512;
        s = ba[c];
        for (int j = 0; j < 512; ++j) s += bq[j] * Wa[(size_t)j * 32 + c];
    }
    g_bc[n] = s;
}

// ---------------- fused stats + transpose + LN -> fp16 q ----------------
#define LN_SMEM (32*514*2 + 2*8*32*4 + 64*4)
__global__ void __launch_bounds__(256) k_lnfuse(const float* __restrict__ fq,
                                                const float* __restrict__ lng,
                                                const float* __restrict__ lnb) {
    extern __shared__ __align__(16) char sm_dyn[];
    __half* tile = (__half*)sm_dyn;
    float* sredS  = (float*)(sm_dyn + 32 * 514 * 2);
    float* sredSS = sredS + 8 * 32;
    float* smean  = sredSS + 8 * 32;
    float* srstd  = smean + 32;
    int b  = blockIdx.y;
    int n0 = blockIdx.x * 32;
    int tid = threadIdx.x;
    int warp = tid >> 5, lane = tid & 31;
    const float* src = fq + (size_t)b * Cc * Nspat + n0 + lane;
    float s = 0.f, ss = 0.f;
    #pragma unroll 8
    for (int it = 0; it < 64; ++it) {
        int c = it * 8 + warp;
        float v = src[(size_t)c * Nspat];
        s += v; ss += v * v;
        tile[lane * 514 + c] = __float2half_rn(v);
    }
    sredS[warp * 32 + lane] = s;
    sredSS[warp * 32 + lane] = ss;
    __syncthreads();
    if (warp == 0) {
        float st = 0.f, sst = 0.f;
        #pragma unroll
        for (int w = 0; w < 8; ++w) {
            st  += sredS[w * 32 + lane];
            sst += sredSS[w * 32 + lane];
        }
        float mu = st * (1.f / Cc);
        float var = sst * (1.f / Cc) - mu * mu;
        smean[lane] = mu;
        srstd[lane] = rsqrtf(var + LN_EPS);
    }
    __syncthreads();
    #pragma unroll
    for (int i = 0; i < 4; ++i) {
        int tok = warp * 4 + i;
        float mu = smean[tok], rs = srstd[tok];
        size_t obase = (size_t)(b * Nspat + n0 + tok) * Cc;
        const __half* row = tile + tok * 514;
        #pragma unroll
        for (int k = 0; k < 4; ++k) {
            int c = lane * 4 + k * 128;
            float2 va = __half22float2(*(const __half2*)(row + c));
            float2 vb = __half22float2(*(const __half2*)(row + c + 2));
            float v0 = (va.x - mu) * rs * lng[c + 0] + lnb[c + 0];
            float v1 = (va.y - mu) * rs * lng[c + 1] + lnb[c + 1];
            float v2 = (vb.x - mu) * rs * lng[c + 2] + lnb[c + 2];
            float v3 = (vb.y - mu) * rs * lng[c + 3] + lnb[c + 3];
            __half2 h01 = __floats2half2_rn(v0, v1);
            __half2 h23 = __floats2half2_rn(v2, v3);
            *(uint2*)(g_q + obase + c) = make_uint2(*(uint32_t*)&h01, *(uint32_t*)&h23);
        }
    }
}

// ---------------- permute f_kv -> (B,NH,D,H,W,HD) as fp16 ----------------
__global__ void k_perm(const float* __restrict__ fkv) {
    __shared__ float s[HDc * 21];
    int blk = blockIdx.x;
    int x = blk % Dim;
    int y = (blk / Dim) % Dim;
    int h = (blk / (Dim * Dim)) % NHc;
    int b = blk / (Dim * Dim * NHc);
    const float* src = fkv + ((size_t)(b * Cc + h * HDc)) * Nspat + (y * Dim + x) * Dim;
    for (int idx = threadIdx.x; idx < HDc * Dim; idx += blockDim.x) {
        int hd = idx / Dim, z = idx - hd * Dim;
        s[hd * 21 + z] = src[(size_t)hd * Nspat + z];
    }
    __syncthreads();
    __half* dst = g_feats + ((size_t)(b * NHc + h) * Nspat) * HDc;
    for (int idx = threadIdx.x; idx < HDc * Dim; idx += blockDim.x) {
        int z = idx / HDc, hd = idx - z * HDc;
        dst[(size_t)((z * Dim + y) * Dim + x) * HDc + hd] = __float2half_rn(s[hd * 21 + z]);
    }
}

// ---------------- trilinear gather + fused softmax + weighted sum (h-major) ----------------
// block's 8 warps = 8 consecutive tokens of the SAME head -> corner rows L1-resident
__global__ void k_sample() {
    int gw   = (blockIdx.x * blockDim.x + threadIdx.x) >> 5;
    int lane = threadIdx.x & 31;
    if (gw >= MTOT * NHc) return;
    int h = gw / MTOT;
    int t = gw - h * MTOT;
    int b = t / Nspat;
    int n = t - b * Nspat;
    int y = n / (Dim * Dim);
    int x = (n / Dim) % Dim;
    int z = n % Dim;
    int gidx = t * NHc + h;

    const float* off = g_off + (size_t)gidx * NPc * 3;
    float4 lg = ((const float4*)g_attn)[gidx];
    float mx = fmaxf(fmaxf(lg.x, lg.y), fmaxf(lg.z, lg.w));
    float e0 = __expf(lg.x - mx), e1 = __expf(lg.y - mx);
    float e2 = __expf(lg.z - mx), e3 = __expf(lg.w - mx);
    float inv = 1.f / (e0 + e1 + e2 + e3);
    float aw[4] = {e0 * inv, e1 * inv, e2 * inv, e3 * inv};

    const __half* feats = g_feats + ((size_t)(b * NHc + h) * Nspat) * HDc;

    float acc0 = 0.f, acc1 = 0.f;
    #pragma unroll
    for (int p = 0; p < NPc; ++p) {
        float ap = aw[p];
        float ix = fminf(fmaxf((float)y + off[p * 3 + 0], 0.f), (float)(Dim - 1));
        float iy = fminf(fmaxf((float)x + off[p * 3 + 1], 0.f), (float)(Dim - 1));
        float iz = fminf(fmaxf((float)z + off[p * 3 + 2], 0.f), (float)(Dim - 1));
        float x0f = floorf(ix), y0f = floorf(iy), z0f = floorf(iz);
        float fx = ix - x0f, fy = iy - y0f, fz = iz - z0f;
        int x0 = (int)x0f, y0 = (int)y0f, z0 = (int)z0f;
        int x1 = min(x0 + 1, Dim - 1);
        int y1 = min(y0 + 1, Dim - 1);
        int z1 = min(z0 + 1, Dim - 1);
        float wx[2] = {1.f - fx, fx};
        float wy[2] = {1.f - fy, fy};
        float wz[2] = {1.f - fz, fz};
        int   xs[2] = {x0, x1}, ys[2] = {y0, y1}, zs[2] = {z0, z1};
        #pragma unroll
        for (int dz = 0; dz < 2; ++dz)
            #pragma unroll
            for (int dy = 0; dy < 2; ++dy)
                #pragma unroll
                for (int dx = 0; dx < 2; ++dx) {
                    float w = ap * wz[dz] * wy[dy] * wx[dx];
                    const __half2* f = (const __half2*)(feats + (size_t)((zs[dz] * Dim + ys[dy]) * Dim + xs[dx]) * HDc);
                    float2 v = __half22float2(f[lane]);
                    acc0 += w * v.x;
                    acc1 += w * v.y;
                }
    }
    *(__half2*)(g_s + (size_t)t * Cc + h * HDc + lane * 2) = __floats2half2_rn(acc0, acc1);
}

// ---------------- host ----------------
extern "C" void kernel_launch(void* const* d_in, const int* in_sizes, int n_in,
                              void* d_out, int out_size) {
    (void)in_sizes; (void)n_in; (void)out_size;
    const float* f_query = (const float*)d_in[0];
    const float* f_kv    = (const float*)d_in[1];
    const float* ln_g    = (const float*)d_in[2];
    const float* ln_b    = (const float*)d_in[3];
    const float* Wq   = (const float*)d_in[4];
    const float* bq   = (const float*)d_in[5];
    const float* Wo1  = (const float*)d_in[6];
    const float* bo1  = (const float*)d_in[7];
    const float* Wo2  = (const float*)d_in[8];
    const float* bo2  = (const float*)d_in[9];
    const float* Wa   = (const float*)d_in[10];
    const float* ba   = (const float*)d_in[11];
    const float* Wout = (const float*)d_in[12];
    const float* bout = (const float*)d_in[13];
    float* out = (float*)d_out;

    float *p_off, *p_attn, *p_bc;
    cudaGetSymbolAddress((void**)&p_off,  g_off);
    cudaGetSymbolAddress((void**)&p_attn, g_attn);
    cudaGetSymbolAddress((void**)&p_bc,   g_bc);
    __half *q, *hid, *sp, *w1, *wo2, *wo;
    cudaGetSymbolAddress((void**)&q, g_q);
    cudaGetSymbolAddress((void**)&hid, g_hid);
    cudaGetSymbolAddress((void**)&sp, g_s);
    cudaGetSymbolAddress((void**)&w1, g_W1);
    cudaGetSymbolAddress((void**)&wo2, g_Wo2);
    cudaGetSymbolAddress((void**)&wo, g_Wout);

    cudaFuncSetAttribute((const void*)k_sgemm<0,2>, cudaFuncAttributeMaxDynamicSharedMemorySize, NS_SMEM);
    cudaFuncSetAttribute((const void*)k_sgemm_dual, cudaFuncAttributeMaxDynamicSharedMemorySize, NS_SMEM);
    cudaFuncSetAttribute((const void*)k_sgemm<0,1>, cudaFuncAttributeMaxDynamicSharedMemorySize, NS_SMEM);
    cudaFuncSetAttribute(k_lnfuse, cudaFuncAttributeMaxDynamicSharedMemorySize, LN_SMEM);

    // one merged prep launch
    k_prep<<<dim3(16, 16, 23), dim3(32, 8)>>>(Wout, Wo2, Wo1, Wa, Wq, bq, bo1, ba);

    // fused stats + transpose + LN -> fp16 q
    k_lnfuse<<<dim3(250, Bc), 256, LN_SMEM>>>(f_query, ln_g, ln_b);
    // permute KV to fp16 channels-last
    k_perm<<<Bc * NHc * Dim * Dim, 256>>>(f_kv);

    // hid = relu(q @ W1[0:512] + bc) -> fp16   (500 blocks)
    k_sgemm<0,2><<<dim3(4, 125), 256, NS_SMEM>>>(q, w1, p_bc, nullptr, hid, Cc);
    // off = clip(hid@Wo2+bo2)  AND  attn = q@W1[512:544]+bc[512:]   (250 blocks, one wave)
    k_sgemm_dual<<<dim3(1, 250), 256, NS_SMEM>>>(hid, wo2, bo2, p_off,
                                                 q, w1 + (size_t)512 * 512, p_bc + 512, p_attn);
    // sampling (softmax fused, h-major locality) -> fp16 samp
    k_sample<<<(MTOT * NHc) * 32 / 256, 256>>>();
    // out = samp @ Wout + bout, staged coalesced transposed store
    k_sgemm<0,1><<<dim3(4, 125), 256, NS_SMEM>>>(sp, wo, bout, out, nullptr, Cc);
}

// round 15
// speedup vs baseline: 1.0516x; 1.0516x over previous
#include <cuda_runtime.h>
#include <cuda_bf16.h>
#include <cuda_fp16.h>
#include <cstdint>

#define Bc 2
#define Cc 512
#define NHc 8
#define NPc 4
#define HDc 64
#define Dim 20
#define Nspat 8000          // 20*20*20
#define MTOT (Bc*Nspat)     // 16000
#define LN_EPS 1e-5f

// ---------------- scratch ----------------
__device__ __align__(16) __half g_q   [(size_t)MTOT*Cc];
__device__ __align__(16) __half g_hid [(size_t)MTOT*Cc];
__device__ __align__(16) __half g_s   [(size_t)MTOT*Cc];
__device__ __align__(16) float g_off [(size_t)MTOT*NHc*NPc*3];
__device__ __align__(16) float g_attn[(size_t)MTOT*NHc*NPc];
__device__ __align__(16) __half g_feats[(size_t)Bc*NHc*Nspat*HDc];
__device__ __align__(256) __half g_W1  [640*512];   // folded [Wo1T;WaT]@Wq
__device__ __align__(256) __half g_Wo2 [128*512];
__device__ __align__(256) __half g_Wout[512*512];
__device__ float g_bc[640];

// ================= helpers =================
__device__ __forceinline__ uint32_t smem_u32(const void* p) {
    uint32_t a;
    asm("{ .reg .u64 t; cvta.to.shared.u64 t, %1; cvt.u32.u64 %0, t; }" : "=r"(a) : "l"(p));
    return a;
}
__device__ __forceinline__ void ldsm4(uint32_t* r, uint32_t addr) {
    asm volatile("ldmatrix.sync.aligned.m8n8.x4.shared.b16 {%0,%1,%2,%3}, [%4];"
        : "=r"(r[0]), "=r"(r[1]), "=r"(r[2]), "=r"(r[3]) : "r"(addr));
}
__device__ __forceinline__ void mma_f16(float* c, const uint32_t* a, const uint32_t* b) {
    asm volatile(
        "mma.sync.aligned.m16n8k16.row.col.f32.f16.f16.f32 "
        "{%0,%1,%2,%3}, {%4,%5,%6,%7}, {%8,%9}, {%0,%1,%2,%3};"
        : "+f"(c[0]), "+f"(c[1]), "+f"(c[2]), "+f"(c[3])
        : "r"(a[0]), "r"(a[1]), "r"(a[2]), "r"(a[3]), "r"(b[0]), "r"(b[1]));
}
#define CPA16(dst, src) \
    asm volatile("cp.async.cg.shared.global [%0], [%1], 16;" :: "r"(dst), "l"(src) : "memory")

// ================= fp16 HMMA GEMM (single-A, BK=32, 3-stage, frag prefetch) =================
// Tile 128x128. Stage: A@0 B@10240 (20480B). 3 stages = 61440B.
#define GM_STAGE 20480
#define NS_SMEM (3*GM_STAGE)   // 61440
#define TR_SMEM (128*129*4)    // 66048 for staged transposed epilogue

// omode: 0 = fp32 row-major (+act 2 clip), 1 = fp32 transposed staged, 2 = relu -> fp16
__device__ __forceinline__ void sgemm_body(
    const __half* __restrict__ AH,
    const __half* __restrict__ Bs,
    const float* __restrict__ bias,
    float* __restrict__ Cf, __half* __restrict__ CH,
    int Nc, int act, int omode, int m0, int n0, char* sm)
{
    constexpr int BOFF = 10240;
    const uint32_t smb = smem_u32(sm);
    const int tid = threadIdx.x;
    const int wid = tid >> 5, lane = tid & 31;
    const int wm = wid >> 1;
    const int wn = wid & 1;

    const int tq = lane >> 3, rr = lane & 7;
    const int a_row = rr + (tq & 1) * 8;
    const int a_col = (tq >> 1) * 8;
    const int b_row = rr + (tq >> 1) * 8;
    const int b_col = (tq & 1) * 8;

    const int r2  = tid >> 1;
    const int kc2 = (tid & 1) * 32;

    const __half* AHp = AH + (size_t)(m0 + r2) * 512 + (tid & 1) * 16;
    const __half* Bp  = Bs + (size_t)(n0 + r2) * 512 + (tid & 1) * 16;

    auto ldAB = [&](int buf, int kt) {
        uint32_t ro = smb + buf * GM_STAGE + r2 * 80 + kc2;
        const int go = kt * 32;
        CPA16(ro,             AHp + go);
        CPA16(ro + 16,        AHp + go + 8);
        CPA16(ro + BOFF,      Bp + go);
        CPA16(ro + BOFF + 16, Bp + go + 8);
        asm volatile("cp.async.commit_group;" ::: "memory");
    };

    float acc[2][8][4];
    #pragma unroll
    for (int mi = 0; mi < 2; ++mi)
        #pragma unroll
        for (int j = 0; j < 8; ++j)
            #pragma unroll
            for (int q = 0; q < 4; ++q) acc[mi][j][q] = 0.f;

    ldAB(0, 0);
    ldAB(1, 1);

    uint32_t ah[2][2][4], bf[2][4][4];
    int buf = 0;
    for (int kt = 0; kt < 16; ++kt) {
        if (kt + 2 < 16) {
            ldAB((buf + 2) % 3, kt + 2);
            asm volatile("cp.async.wait_group 2;" ::: "memory");
        } else if (kt + 1 < 16) {
            asm volatile("cp.async.wait_group 1;" ::: "memory");
        } else {
            asm volatile("cp.async.wait_group 0;" ::: "memory");
        }
        __syncthreads();
        uint32_t abase = smb + buf * GM_STAGE;
        uint32_t bbase = abase + BOFF;
        // fragment loader for k-chunk kc into slot s
        auto ldfr = [&](int s, int kc) {
            #pragma unroll
            for (int mi = 0; mi < 2; ++mi) {
                uint32_t ad = abase + (uint32_t)(wm * 32 + mi * 16 + a_row) * 80 + (kc + a_col) * 2;
                ldsm4(ah[s][mi], ad);
            }
            #pragma unroll
            for (int p = 0; p < 4; ++p) {
                uint32_t bd = bbase + (uint32_t)(wn * 64 + p * 16 + b_row) * 80 + (kc + b_col) * 2;
                ldsm4(bf[s][p], bd);
            }
        };
        ldfr(0, 0);
        #pragma unroll
        for (int ks = 0; ks < 2; ++ks) {
            if (ks == 0) ldfr(1, 16);   // prefetch ks=1 frags while ks=0 MMAs issue
            #pragma unroll
            for (int mi = 0; mi < 2; ++mi)
                #pragma unroll
                for (int j = 0; j < 8; ++j)
                    mma_f16(acc[mi][j], ah[ks][mi], &bf[ks][j >> 1][(j & 1) * 2]);
        }
        __syncthreads();
        buf = (buf + 1) % 3;
    }

    if (omode == 1) {
        float* smf = (float*)sm;   // [128][129]
        #pragma unroll
        for (int mi = 0; mi < 2; ++mi) {
            #pragma unroll
            for (int j = 0; j < 8; ++j) {
                int c0 = wn * 64 + j * 8 + (lane & 3) * 2;
                float b0 = bias[n0 + c0], b1 = bias[n0 + c0 + 1];
                #pragma unroll
                for (int half = 0; half < 2; ++half) {
                    int r = wm * 32 + mi * 16 + (lane >> 2) + half * 8;
                    smf[r * 129 + c0]     = acc[mi][j][half * 2 + 0] + b0;
                    smf[r * 129 + c0 + 1] = acc[mi][j][half * 2 + 1] + b1;
                }
            }
        }
        __syncthreads();
        #pragma unroll 4
        for (int i = 0; i < 64; ++i) {
            int idx = i * 256 + tid;
            int cl = idx >> 7, rl = idx & 127;
            int row = m0 + rl;
            int b = row / Nspat, n = row - b * Nspat;
            Cf[((size_t)(b * Cc + n0 + cl)) * Nspat + n] = smf[rl * 129 + cl];
        }
        return;
    }

    #pragma unroll
    for (int mi = 0; mi < 2; ++mi) {
        int row0 = m0 + wm * 32 + mi * 16 + (lane >> 2);
        #pragma unroll
        for (int j = 0; j < 8; ++j) {
            int col0 = n0 + wn * 64 + j * 8 + (lane & 3) * 2;
            if (col0 >= Nc) continue;
            float b0 = bias[col0], b1 = bias[col0 + 1];
            #pragma unroll
            for (int half = 0; half < 2; ++half) {
                int row = row0 + half * 8;
                float v0 = acc[mi][j][half * 2 + 0] + b0;
                float v1 = acc[mi][j][half * 2 + 1] + b1;
                if (omode == 2) {
                    v0 = fmaxf(v0, 0.f); v1 = fmaxf(v1, 0.f);
                    *(__half2*)(CH + (size_t)row * Nc + col0) = __floats2half2_rn(v0, v1);
                } else {
                    if (act == 2) {
                        v0 = fminf(fmaxf(v0, -3.f), 3.f);
                        v1 = fminf(fmaxf(v1, -3.f), 3.f);
                    }
                    *(float2*)(Cf + (size_t)row * Nc + col0) = make_float2(v0, v1);
                }
            }
        }
    }
}

template<int ACT, int OMODE>
__global__ void __launch_bounds__(256, 2) k_sgemm(
    const __half* __restrict__ AH,
    const __half* __restrict__ Bs,
    const float* __restrict__ bias,
    float* __restrict__ Cf, __half* __restrict__ CH,
    int Nc)
{
    extern __shared__ __align__(1024) char sm_dyn[];
    sgemm_body(AH, Bs, bias, Cf, CH, Nc, ACT, OMODE,
               blockIdx.y * 128, blockIdx.x * 128, sm_dyn);
}

// dual: blocks [0,125) -> off = clip(hid@Wo2+bo2); [125,250) -> attn = q@W1[512:]+bc[512:]
__global__ void __launch_bounds__(256, 2) k_sgemm_dual(
    const __half* __restrict__ hid, const __half* __restrict__ wo2, const float* __restrict__ bo2,
    float* __restrict__ off,
    const __half* __restrict__ q, const __half* __restrict__ w1a, const float* __restrict__ bca,
    float* __restrict__ attn)
{
    extern __shared__ __align__(1024) char sm_dyn[];
    int by = blockIdx.y;
    if (by < 125)
        sgemm_body(hid, wo2, bo2, off, nullptr, NHc * NPc * 3, 2, 0, by * 128, 0, sm_dyn);
    else
        sgemm_body(q, w1a, bca, attn, nullptr, NHc * NPc, 0, 0, (by - 125) * 128, 0, sm_dyn);
}

// ---------------- merged prep ----------------
__global__ void k_prep(const float* __restrict__ Wout, const float* __restrict__ Wo2,
                       const float* __restrict__ Wo1,  const float* __restrict__ Wa,
                       const float* __restrict__ Wq,
                       const float* __restrict__ bq,   const float* __restrict__ bo1,
                       const float* __restrict__ ba) {
    __shared__ float T1[32][33];
    __shared__ float T2[32][33];
    int z = blockIdx.z;
    int tx = threadIdx.x, ty = threadIdx.y;
    if (z < 2) {
        const float* W = (z == 0) ? Wout : Wo2;
        __half* Hd = (z == 0) ? g_Wout : g_Wo2;
        int Ncols = (z == 0) ? 512 : NHc * NPc * 3;
        int Npad  = (z == 0) ? 512 : 128;
        int k0 = blockIdx.y * 32, n0 = blockIdx.x * 32;
        if (n0 >= Npad) return;
        #pragma unroll
        for (int i = 0; i < 32; i += 8) {
            int k = k0 + ty + i, n = n0 + tx;
            T1[ty + i][tx] = (n < Ncols) ? W[(size_t)k * Ncols + n] : 0.f;
        }
        __syncthreads();
        #pragma unroll
        for (int i = 0; i < 32; i += 8) {
            int n = n0 + ty + i, k = k0 + tx;
            Hd[(size_t)n * 512 + k] = __float2half_rn(T1[tx][ty + i]);
        }
        return;
    }
    if (z < 22) {
        if (blockIdx.y != 0) return;
        int n0 = (z - 2) * 32, j0 = blockIdx.x * 32;
        float acc[4] = {0.f, 0.f, 0.f, 0.f};
        for (int k0 = 0; k0 < 512; k0 += 32) {
            #pragma unroll
            for (int i = 0; i < 32; i += 8) {
                int k = k0 + ty + i, n = n0 + tx;
                float v = 0.f;
                if (n < 512)      v = Wo1[(size_t)k * 512 + n];
                else if (n < 544) v = Wa[(size_t)k * 32 + (n - 512)];
                T1[ty + i][tx] = v;
                T2[ty + i][tx] = Wq[(size_t)(j0 + ty + i) * 512 + k0 + tx];
            }
            __syncthreads();
            #pragma unroll 8
            for (int k = 0; k < 32; ++k) {
                float t1 = T1[k][tx];
                #pragma unroll
                for (int r = 0; r < 4; ++r) acc[r] += t1 * T2[ty + 8 * r][k];
            }
            __syncthreads();
        }
        #pragma unroll
        for (int r = 0; r < 4; ++r)
            g_W1[(size_t)(n0 + tx) * 512 + j0 + ty + 8 * r] = __float2half_rn(acc[r]);
        return;
    }
    if (blockIdx.y != 0 || blockIdx.x >= 3) return;
    int n = blockIdx.x * 256 + ty * 32 + tx;
    if (n >= 640) return;
    float s = 0.f;
    if (n < 512) {
        s = bo1[n];
        for (int j = 0; j < 512; ++j) s += bq[j] * Wo1[(size_t)j * 512 + n];
    } else if (n < 544) {
        int c = n - 512;
        s = ba[c];
        for (int j = 0; j < 512; ++j) s += bq[j] * Wa[(size_t)j * 32 + c];
    }
    g_bc[n] = s;
}

// ---------------- fused stats + transpose + LN -> fp16 q ----------------
#define LN_SMEM (32*514*2 + 2*8*32*4 + 64*4)
__global__ void __launch_bounds__(256) k_lnfuse(const float* __restrict__ fq,
                                                const float* __restrict__ lng,
                                                const float* __restrict__ lnb) {
    extern __shared__ __align__(16) char sm_dyn[];
    __half* tile = (__half*)sm_dyn;
    float* sredS  = (float*)(sm_dyn + 32 * 514 * 2);
    float* sredSS = sredS + 8 * 32;
    float* smean  = sredSS + 8 * 32;
    float* srstd  = smean + 32;
    int b  = blockIdx.y;
    int n0 = blockIdx.x * 32;
    int tid = threadIdx.x;
    int warp = tid >> 5, lane = tid & 31;
    const float* src = fq + (size_t)b * Cc * Nspat + n0 + lane;
    float s = 0.f, ss = 0.f;
    #pragma unroll 8
    for (int it = 0; it < 64; ++it) {
        int c = it * 8 + warp;
        float v = src[(size_t)c * Nspat];
        s += v; ss += v * v;
        tile[lane * 514 + c] = __float2half_rn(v);
    }
    sredS[warp * 32 + lane] = s;
    sredSS[warp * 32 + lane] = ss;
    __syncthreads();
    if (warp == 0) {
        float st = 0.f, sst = 0.f;
        #pragma unroll
        for (int w = 0; w < 8; ++w) {
            st  += sredS[w * 32 + lane];
            sst += sredSS[w * 32 + lane];
        }
        float mu = st * (1.f / Cc);
        float var = sst * (1.f / Cc) - mu * mu;
        smean[lane] = mu;
        srstd[lane] = rsqrtf(var + LN_EPS);
    }
    __syncthreads();
    #pragma unroll
    for (int i = 0; i < 4; ++i) {
        int tok = warp * 4 + i;
        float mu = smean[tok], rs = srstd[tok];
        size_t obase = (size_t)(b * Nspat + n0 + tok) * Cc;
        const __half* row = tile + tok * 514;
        #pragma unroll
        for (int k = 0; k < 4; ++k) {
            int c = lane * 4 + k * 128;
            float2 va = __half22float2(*(const __half2*)(row + c));
            float2 vb = __half22float2(*(const __half2*)(row + c + 2));
            float v0 = (va.x - mu) * rs * lng[c + 0] + lnb[c + 0];
            float v1 = (va.y - mu) * rs * lng[c + 1] + lnb[c + 1];
            float v2 = (vb.x - mu) * rs * lng[c + 2] + lnb[c + 2];
            float v3 = (vb.y - mu) * rs * lng[c + 3] + lnb[c + 3];
            __half2 h01 = __floats2half2_rn(v0, v1);
            __half2 h23 = __floats2half2_rn(v2, v3);
            *(uint2*)(g_q + obase + c) = make_uint2(*(uint32_t*)&h01, *(uint32_t*)&h23);
        }
    }
}

// ---------------- permute f_kv -> (B,NH,D,H,W,HD) as fp16 ----------------
__global__ void k_perm(const float* __restrict__ fkv) {
    __shared__ float s[HDc * 21];
    int blk = blockIdx.x;
    int x = blk % Dim;
    int y = (blk / Dim) % Dim;
    int h = (blk / (Dim * Dim)) % NHc;
    int b = blk / (Dim * Dim * NHc);
    const float* src = fkv + ((size_t)(b * Cc + h * HDc)) * Nspat + (y * Dim + x) * Dim;
    for (int idx = threadIdx.x; idx < HDc * Dim; idx += blockDim.x) {
        int hd = idx / Dim, z = idx - hd * Dim;
        s[hd * 21 + z] = src[(size_t)hd * Nspat + z];
    }
    __syncthreads();
    __half* dst = g_feats + ((size_t)(b * NHc + h) * Nspat) * HDc;
    for (int idx = threadIdx.x; idx < HDc * Dim; idx += blockDim.x) {
        int z = idx / HDc, hd = idx - z * HDc;
        dst[(size_t)((z * Dim + y) * Dim + x) * HDc + hd] = __float2half_rn(s[hd * 21 + z]);
    }
}

// ---------------- trilinear gather + fused softmax + weighted sum (t-major) ----------------
__global__ void k_sample() {
    int gw   = (blockIdx.x * blockDim.x + threadIdx.x) >> 5;
    int lane = threadIdx.x & 31;
    if (gw >= MTOT * NHc) return;
    int h = gw % NHc;
    int t = gw / NHc;
    int b = t / Nspat;
    int n = t - b * Nspat;
    int y = n / (Dim * Dim);
    int x = (n / Dim) % Dim;
    int z = n % Dim;

    const float* off = g_off + (size_t)gw * NPc * 3;
    float4 lg = ((const float4*)g_attn)[gw];
    float mx = fmaxf(fmaxf(lg.x, lg.y), fmaxf(lg.z, lg.w));
    float e0 = __expf(lg.x - mx), e1 = __expf(lg.y - mx);
    float e2 = __expf(lg.z - mx), e3 = __expf(lg.w - mx);
    float inv = 1.f / (e0 + e1 + e2 + e3);
    float aw[4] = {e0 * inv, e1 * inv, e2 * inv, e3 * inv};

    const __half* feats = g_feats + ((size_t)(b * NHc + h) * Nspat) * HDc;

    float acc0 = 0.f, acc1 = 0.f;
    #pragma unroll
    for (int p = 0; p < NPc; ++p) {
        float ap = aw[p];
        float ix = fminf(fmaxf((float)y + off[p * 3 + 0], 0.f), (float)(Dim - 1));
        float iy = fminf(fmaxf((float)x + off[p * 3 + 1], 0.f), (float)(Dim - 1));
        float iz = fminf(fmaxf((float)z + off[p * 3 + 2], 0.f), (float)(Dim - 1));
        float x0f = floorf(ix), y0f = floorf(iy), z0f = floorf(iz);
        float fx = ix - x0f, fy = iy - y0f, fz = iz - z0f;
        int x0 = (int)x0f, y0 = (int)y0f, z0 = (int)z0f;
        int x1 = min(x0 + 1, Dim - 1);
        int y1 = min(y0 + 1, Dim - 1);
        int z1 = min(z0 + 1, Dim - 1);
        float wx[2] = {1.f - fx, fx};
        float wy[2] = {1.f - fy, fy};
        float wz[2] = {1.f - fz, fz};
        int   xs[2] = {x0, x1}, ys[2] = {y0, y1}, zs[2] = {z0, z1};
        #pragma unroll
        for (int dz = 0; dz < 2; ++dz)
            #pragma unroll
            for (int dy = 0; dy < 2; ++dy)
                #pragma unroll
                for (int dx = 0; dx < 2; ++dx) {
                    float w = ap * wz[dz] * wy[dy] * wx[dx];
                    const __half2* f = (const __half2*)(feats + (size_t)((zs[dz] * Dim + ys[dy]) * Dim + xs[dx]) * HDc);
                    float2 v = __half22float2(f[lane]);
                    acc0 += w * v.x;
                    acc1 += w * v.y;
                }
    }
    *(__half2*)(g_s + (size_t)t * Cc + h * HDc + lane * 2) = __floats2half2_rn(acc0, acc1);
}

// ---------------- host ----------------
extern "C" void kernel_launch(void* const* d_in, const int* in_sizes, int n_in,
                              void* d_out, int out_size) {
    (void)in_sizes; (void)n_in; (void)out_size;
    const float* f_query = (const float*)d_in[0];
    const float* f_kv    = (const float*)d_in[1];
    const float* ln_g    = (const float*)d_in[2];
    const float* ln_b    = (const float*)d_in[3];
    const float* Wq   = (const float*)d_in[4];
    const float* bq   = (const float*)d_in[5];
    const float* Wo1  = (const float*)d_in[6];
    const float* bo1  = (const float*)d_in[7];
    const float* Wo2  = (const float*)d_in[8];
    const float* bo2  = (const float*)d_in[9];
    const float* Wa   = (const float*)d_in[10];
    const float* ba   = (const float*)d_in[11];
    const float* Wout = (const float*)d_in[12];
    const float* bout = (const float*)d_in[13];
    float* out = (float*)d_out;

    float *p_off, *p_attn, *p_bc;
    cudaGetSymbolAddress((void**)&p_off,  g_off);
    cudaGetSymbolAddress((void**)&p_attn, g_attn);
    cudaGetSymbolAddress((void**)&p_bc,   g_bc);
    __half *q, *hid, *sp, *w1, *wo2, *wo;
    cudaGetSymbolAddress((void**)&q, g_q);
    cudaGetSymbolAddress((void**)&hid, g_hid);
    cudaGetSymbolAddress((void**)&sp, g_s);
    cudaGetSymbolAddress((void**)&w1, g_W1);
    cudaGetSymbolAddress((void**)&wo2, g_Wo2);
    cudaGetSymbolAddress((void**)&wo, g_Wout);

    cudaFuncSetAttribute((const void*)k_sgemm<0,2>, cudaFuncAttributeMaxDynamicSharedMemorySize, NS_SMEM);
    cudaFuncSetAttribute((const void*)k_sgemm_dual, cudaFuncAttributeMaxDynamicSharedMemorySize, NS_SMEM);
    cudaFuncSetAttribute((const void*)k_sgemm<0,1>, cudaFuncAttributeMaxDynamicSharedMemorySize, TR_SMEM);
    cudaFuncSetAttribute(k_lnfuse, cudaFuncAttributeMaxDynamicSharedMemorySize, LN_SMEM);

    // one merged prep launch
    k_prep<<<dim3(16, 16, 23), dim3(32, 8)>>>(Wout, Wo2, Wo1, Wa, Wq, bq, bo1, ba);

    // fused stats + transpose + LN -> fp16 q
    k_lnfuse<<<dim3(250, Bc), 256, LN_SMEM>>>(f_query, ln_g, ln_b);
    // permute KV to fp16 channels-last
    k_perm<<<Bc * NHc * Dim * Dim, 256>>>(f_kv);

    // hid = relu(q @ W1[0:512] + bc) -> fp16   (500 blocks)
    k_sgemm<0,2><<<dim3(4, 125), 256, NS_SMEM>>>(q, w1, p_bc, nullptr, hid, Cc);
    // off = clip(hid@Wo2+bo2)  AND  attn = q@W1[512:544]+bc[512:]   (250 blocks, one wave)
    k_sgemm_dual<<<dim3(1, 250), 256, NS_SMEM>>>(hid, wo2, bo2, p_off,
                                                 q, w1 + (size_t)512 * 512, p_bc + 512, p_attn);
    // sampling (softmax fused) -> fp16 samp
    k_sample<<<(MTOT * NHc) * 32 / 256, 256>>>();
    // out = samp @ Wout + bout, staged coalesced transposed store
    k_sgemm<0,1><<<dim3(4, 125), 256, TR_SMEM>>>(sp, wo, bout, out, nullptr, Cc);
}

// round 16
// speedup vs baseline: 1.0856x; 1.0324x over previous
#include <cuda_runtime.h>
#include <cuda_bf16.h>
#include <cuda_fp16.h>
#include <cstdint>

#define Bc 2
#define Cc 512
#define NHc 8
#define NPc 4
#define HDc 64
#define Dim 20
#define Nspat 8000          // 20*20*20
#define MTOT (Bc*Nspat)     // 16000
#define LN_EPS 1e-5f

// ---------------- scratch ----------------
__device__ __align__(16) __half g_q   [(size_t)MTOT*Cc];
__device__ __align__(16) __half g_hid [(size_t)MTOT*Cc];
__device__ __align__(16) __half g_s   [(size_t)MTOT*Cc];
__device__ __align__(16) float g_off [(size_t)MTOT*NHc*NPc*3];
__device__ __align__(16) float g_attn[(size_t)MTOT*NHc*NPc];
__device__ __align__(16) __half g_feats[(size_t)Bc*NHc*Nspat*HDc];
__device__ __align__(256) __half g_W1  [640*512];   // folded [Wo1T;WaT]@Wq
__device__ __align__(256) __half g_Wo2 [128*512];
__device__ __align__(256) __half g_Wout[512*512];
__device__ float g_bc[640];

// ================= helpers =================
__device__ __forceinline__ uint32_t smem_u32(const void* p) {
    uint32_t a;
    asm("{ .reg .u64 t; cvta.to.shared.u64 t, %1; cvt.u32.u64 %0, t; }" : "=r"(a) : "l"(p));
    return a;
}
__device__ __forceinline__ void ldsm4(uint32_t* r, uint32_t addr) {
    asm volatile("ldmatrix.sync.aligned.m8n8.x4.shared.b16 {%0,%1,%2,%3}, [%4];"
        : "=r"(r[0]), "=r"(r[1]), "=r"(r[2]), "=r"(r[3]) : "r"(addr));
}
__device__ __forceinline__ void mma_f16(float* c, const uint32_t* a, const uint32_t* b) {
    asm volatile(
        "mma.sync.aligned.m16n8k16.row.col.f32.f16.f16.f32 "
        "{%0,%1,%2,%3}, {%4,%5,%6,%7}, {%8,%9}, {%0,%1,%2,%3};"
        : "+f"(c[0]), "+f"(c[1]), "+f"(c[2]), "+f"(c[3])
        : "r"(a[0]), "r"(a[1]), "r"(a[2]), "r"(a[3]), "r"(b[0]), "r"(b[1]));
}
#define CPA16(dst, src) \
    asm volatile("cp.async.cg.shared.global [%0], [%1], 16;" :: "r"(dst), "l"(src) : "memory")

// ================= fp16 HMMA GEMM (single-A, BK=32, 3-stage, frag prefetch) =================
#define GM_STAGE 20480
#define NS_SMEM (3*GM_STAGE)   // 61440
#define TR_SMEM (128*129*4)    // 66048 for staged transposed epilogue

// omode: 0 = fp32 row-major (+act 2 clip), 1 = fp32 transposed staged, 2 = relu -> fp16
__device__ __forceinline__ void sgemm_body(
    const __half* __restrict__ AH,
    const __half* __restrict__ Bs,
    const float* __restrict__ bias,
    float* __restrict__ Cf, __half* __restrict__ CH,
    int Nc, int act, int omode, int m0, int n0, char* sm)
{
    constexpr int BOFF = 10240;
    const uint32_t smb = smem_u32(sm);
    const int tid = threadIdx.x;
    const int wid = tid >> 5, lane = tid & 31;
    const int wm = wid >> 1;
    const int wn = wid & 1;

    const int tq = lane >> 3, rr = lane & 7;
    const int a_row = rr + (tq & 1) * 8;
    const int a_col = (tq >> 1) * 8;
    const int b_row = rr + (tq >> 1) * 8;
    const int b_col = (tq & 1) * 8;

    const int r2  = tid >> 1;
    const int kc2 = (tid & 1) * 32;

    const __half* AHp = AH + (size_t)(m0 + r2) * 512 + (tid & 1) * 16;
    const __half* Bp  = Bs + (size_t)(n0 + r2) * 512 + (tid & 1) * 16;

    auto ldAB = [&](int buf, int kt) {
        uint32_t ro = smb + buf * GM_STAGE + r2 * 80 + kc2;
        const int go = kt * 32;
        CPA16(ro,             AHp + go);
        CPA16(ro + 16,        AHp + go + 8);
        CPA16(ro + BOFF,      Bp + go);
        CPA16(ro + BOFF + 16, Bp + go + 8);
        asm volatile("cp.async.commit_group;" ::: "memory");
    };

    float acc[2][8][4];
    #pragma unroll
    for (int mi = 0; mi < 2; ++mi)
        #pragma unroll
        for (int j = 0; j < 8; ++j)
            #pragma unroll
            for (int q = 0; q < 4; ++q) acc[mi][j][q] = 0.f;

    ldAB(0, 0);
    ldAB(1, 1);

    uint32_t ah[2][2][4], bf[2][4][4];
    int buf = 0;
    for (int kt = 0; kt < 16; ++kt) {
        if (kt + 2 < 16) {
            ldAB((buf + 2) % 3, kt + 2);
            asm volatile("cp.async.wait_group 2;" ::: "memory");
        } else if (kt + 1 < 16) {
            asm volatile("cp.async.wait_group 1;" ::: "memory");
        } else {
            asm volatile("cp.async.wait_group 0;" ::: "memory");
        }
        __syncthreads();
        uint32_t abase = smb + buf * GM_STAGE;
        uint32_t bbase = abase + BOFF;
        auto ldfr = [&](int s, int kc) {
            #pragma unroll
            for (int mi = 0; mi < 2; ++mi) {
                uint32_t ad = abase + (uint32_t)(wm * 32 + mi * 16 + a_row) * 80 + (kc + a_col) * 2;
                ldsm4(ah[s][mi], ad);
            }
            #pragma unroll
            for (int p = 0; p < 4; ++p) {
                uint32_t bd = bbase + (uint32_t)(wn * 64 + p * 16 + b_row) * 80 + (kc + b_col) * 2;
                ldsm4(bf[s][p], bd);
            }
        };
        ldfr(0, 0);
        #pragma unroll
        for (int ks = 0; ks < 2; ++ks) {
            if (ks == 0) ldfr(1, 16);
            #pragma unroll
            for (int mi = 0; mi < 2; ++mi)
                #pragma unroll
                for (int j = 0; j < 8; ++j)
                    mma_f16(acc[mi][j], ah[ks][mi], &bf[ks][j >> 1][(j & 1) * 2]);
        }
        __syncthreads();
        buf = (buf + 1) % 3;
    }

    if (omode == 1) {
        float* smf = (float*)sm;   // [128][129]
        #pragma unroll
        for (int mi = 0; mi < 2; ++mi) {
            #pragma unroll
            for (int j = 0; j < 8; ++j) {
                int c0 = wn * 64 + j * 8 + (lane & 3) * 2;
                float b0 = bias[n0 + c0], b1 = bias[n0 + c0 + 1];
                #pragma unroll
                for (int half = 0; half < 2; ++half) {
                    int r = wm * 32 + mi * 16 + (lane >> 2) + half * 8;
                    smf[r * 129 + c0]     = acc[mi][j][half * 2 + 0] + b0;
                    smf[r * 129 + c0 + 1] = acc[mi][j][half * 2 + 1] + b1;
                }
            }
        }
        __syncthreads();
        #pragma unroll 4
        for (int i = 0; i < 64; ++i) {
            int idx = i * 256 + tid;
            int cl = idx >> 7, rl = idx & 127;
            int row = m0 + rl;
            int b = row / Nspat, n = row - b * Nspat;
            Cf[((size_t)(b * Cc + n0 + cl)) * Nspat + n] = smf[rl * 129 + cl];
        }
        return;
    }

    #pragma unroll
    for (int mi = 0; mi < 2; ++mi) {
        int row0 = m0 + wm * 32 + mi * 16 + (lane >> 2);
        #pragma unroll
        for (int j = 0; j < 8; ++j) {
            int col0 = n0 + wn * 64 + j * 8 + (lane & 3) * 2;
            if (col0 >= Nc) continue;
            float b0 = bias[col0], b1 = bias[col0 + 1];
            #pragma unroll
            for (int half = 0; half < 2; ++half) {
                int row = row0 + half * 8;
                float v0 = acc[mi][j][half * 2 + 0] + b0;
                float v1 = acc[mi][j][half * 2 + 1] + b1;
                if (omode == 2) {
                    v0 = fmaxf(v0, 0.f); v1 = fmaxf(v1, 0.f);
                    *(__half2*)(CH + (size_t)row * Nc + col0) = __floats2half2_rn(v0, v1);
                } else {
                    if (act == 2) {
                        v0 = fminf(fmaxf(v0, -3.f), 3.f);
                        v1 = fminf(fmaxf(v1, -3.f), 3.f);
                    }
                    *(float2*)(Cf + (size_t)row * Nc + col0) = make_float2(v0, v1);
                }
            }
        }
    }
}

template<int ACT, int OMODE>
__global__ void __launch_bounds__(256, 2) k_sgemm(
    const __half* __restrict__ AH,
    const __half* __restrict__ Bs,
    const float* __restrict__ bias,
    float* __restrict__ Cf, __half* __restrict__ CH,
    int Nc)
{
    extern __shared__ __align__(1024) char sm_dyn[];
    sgemm_body(AH, Bs, bias, Cf, CH, Nc, ACT, OMODE,
               blockIdx.y * 128, blockIdx.x * 128, sm_dyn);
}

// dual: blocks [0,125) -> off = clip(hid@Wo2+bo2); [125,250) -> attn = q@W1[512:]+bc[512:]
__global__ void __launch_bounds__(256, 2) k_sgemm_dual(
    const __half* __restrict__ hid, const __half* __restrict__ wo2, const float* __restrict__ bo2,
    float* __restrict__ off,
    const __half* __restrict__ q, const __half* __restrict__ w1a, const float* __restrict__ bca,
    float* __restrict__ attn)
{
    extern __shared__ __align__(1024) char sm_dyn[];
    int by = blockIdx.y;
    if (by < 125)
        sgemm_body(hid, wo2, bo2, off, nullptr, NHc * NPc * 3, 2, 0, by * 128, 0, sm_dyn);
    else
        sgemm_body(q, w1a, bca, attn, nullptr, NHc * NPc, 0, 0, (by - 125) * 128, 0, sm_dyn);
}

// ---------------- merged prep + KV permute ----------------
// grid (16,16,48), block (32,8) = 256 thr:
//   z==0 -> Wout transpose; z==1 -> Wo2 transpose
//   z in [2,22) -> wfold row-group n0=(z-2)*32, j0=bx*32 (by==0 only)
//   z==22 -> bias (by==0, bx<3)
//   z in [23,48) -> KV permute, blk = (z-23)*256 + by*16 + bx
__global__ void k_prep(const float* __restrict__ Wout, const float* __restrict__ Wo2,
                       const float* __restrict__ Wo1,  const float* __restrict__ Wa,
                       const float* __restrict__ Wq,
                       const float* __restrict__ bq,   const float* __restrict__ bo1,
                       const float* __restrict__ ba,
                       const float* __restrict__ fkv) {
    __shared__ float T1[32][33];
    __shared__ float T2[32][33];
    __shared__ float PS[HDc * 21];
    int z = blockIdx.z;
    int tx = threadIdx.x, ty = threadIdx.y;
    int tid = ty * 32 + tx;
    if (z >= 23) {
        // KV permute: (B,NH,HD,H,W,D) -> (B,NH,D,H,W,HD) fp16
        int blk = (z - 23) * 256 + blockIdx.y * 16 + blockIdx.x;
        int x = blk % Dim;
        int y = (blk / Dim) % Dim;
        int h = (blk / (Dim * Dim)) % NHc;
        int b = blk / (Dim * Dim * NHc);
        const float* src = fkv + ((size_t)(b * Cc + h * HDc)) * Nspat + (y * Dim + x) * Dim;
        for (int idx = tid; idx < HDc * Dim; idx += 256) {
            int hd = idx / Dim, zz = idx - hd * Dim;
            PS[hd * 21 + zz] = src[(size_t)hd * Nspat + zz];
        }
        __syncthreads();
        __half* dst = g_feats + ((size_t)(b * NHc + h) * Nspat) * HDc;
        for (int idx = tid; idx < HDc * Dim; idx += 256) {
            int zz = idx / HDc, hd = idx - zz * HDc;
            dst[(size_t)((zz * Dim + y) * Dim + x) * HDc + hd] = __float2half_rn(PS[hd * 21 + zz]);
        }
        return;
    }
    if (z < 2) {
        const float* W = (z == 0) ? Wout : Wo2;
        __half* Hd = (z == 0) ? g_Wout : g_Wo2;
        int Ncols = (z == 0) ? 512 : NHc * NPc * 3;
        int Npad  = (z == 0) ? 512 : 128;
        int k0 = blockIdx.y * 32, n0 = blockIdx.x * 32;
        if (n0 >= Npad) return;
        #pragma unroll
        for (int i = 0; i < 32; i += 8) {
            int k = k0 + ty + i, n = n0 + tx;
            T1[ty + i][tx] = (n < Ncols) ? W[(size_t)k * Ncols + n] : 0.f;
        }
        __syncthreads();
        #pragma unroll
        for (int i = 0; i < 32; i += 8) {
            int n = n0 + ty + i, k = k0 + tx;
            Hd[(size_t)n * 512 + k] = __float2half_rn(T1[tx][ty + i]);
        }
        return;
    }
    if (z < 22) {
        if (blockIdx.y != 0) return;
        int n0 = (z - 2) * 32, j0 = blockIdx.x * 32;
        float acc[4] = {0.f, 0.f, 0.f, 0.f};
        for (int k0 = 0; k0 < 512; k0 += 32) {
            #pragma unroll
            for (int i = 0; i < 32; i += 8) {
                int k = k0 + ty + i, n = n0 + tx;
                float v = 0.f;
                if (n < 512)      v = Wo1[(size_t)k * 512 + n];
                else if (n < 544) v = Wa[(size_t)k * 32 + (n - 512)];
                T1[ty + i][tx] = v;
                T2[ty + i][tx] = Wq[(size_t)(j0 + ty + i) * 512 + k0 + tx];
            }
            __syncthreads();
            #pragma unroll 8
            for (int k = 0; k < 32; ++k) {
                float t1 = T1[k][tx];
                #pragma unroll
                for (int r = 0; r < 4; ++r) acc[r] += t1 * T2[ty + 8 * r][k];
            }
            __syncthreads();
        }
        #pragma unroll
        for (int r = 0; r < 4; ++r)
            g_W1[(size_t)(n0 + tx) * 512 + j0 + ty + 8 * r] = __float2half_rn(acc[r]);
        return;
    }
    // z == 22: bias
    if (blockIdx.y != 0 || blockIdx.x >= 3) return;
    int n = blockIdx.x * 256 + tid;
    if (n >= 640) return;
    float s = 0.f;
    if (n < 512) {
        s = bo1[n];
        for (int j = 0; j < 512; ++j) s += bq[j] * Wo1[(size_t)j * 512 + n];
    } else if (n < 544) {
        int c = n - 512;
        s = ba[c];
        for (int j = 0; j < 512; ++j) s += bq[j] * Wa[(size_t)j * 32 + c];
    }
    g_bc[n] = s;
}

// ---------------- fused stats + transpose + LN -> fp16 q ----------------
#define LN_SMEM (32*514*2 + 2*8*32*4 + 64*4)
__global__ void __launch_bounds__(256) k_lnfuse(const float* __restrict__ fq,
                                                const float* __restrict__ lng,
                                                const float* __restrict__ lnb) {
    extern __shared__ __align__(16) char sm_dyn[];
    __half* tile = (__half*)sm_dyn;
    float* sredS  = (float*)(sm_dyn + 32 * 514 * 2);
    float* sredSS = sredS + 8 * 32;
    float* smean  = sredSS + 8 * 32;
    float* srstd  = smean + 32;
    int b  = blockIdx.y;
    int n0 = blockIdx.x * 32;
    int tid = threadIdx.x;
    int warp = tid >> 5, lane = tid & 31;
    const float* src = fq + (size_t)b * Cc * Nspat + n0 + lane;
    float s = 0.f, ss = 0.f;
    #pragma unroll 8
    for (int it = 0; it < 64; ++it) {
        int c = it * 8 + warp;
        float v = src[(size_t)c * Nspat];
        s += v; ss += v * v;
        tile[lane * 514 + c] = __float2half_rn(v);
    }
    sredS[warp * 32 + lane] = s;
    sredSS[warp * 32 + lane] = ss;
    __syncthreads();
    if (warp == 0) {
        float st = 0.f, sst = 0.f;
        #pragma unroll
        for (int w = 0; w < 8; ++w) {
            st  += sredS[w * 32 + lane];
            sst += sredSS[w * 32 + lane];
        }
        float mu = st * (1.f / Cc);
        float var = sst * (1.f / Cc) - mu * mu;
        smean[lane] = mu;
        srstd[lane] = rsqrtf(var + LN_EPS);
    }
    __syncthreads();
    #pragma unroll
    for (int i = 0; i < 4; ++i) {
        int tok = warp * 4 + i;
        float mu = smean[tok], rs = srstd[tok];
        size_t obase = (size_t)(b * Nspat + n0 + tok) * Cc;
        const __half* row = tile + tok * 514;
        #pragma unroll
        for (int k = 0; k < 4; ++k) {
            int c = lane * 4 + k * 128;
            float2 va = __half22float2(*(const __half2*)(row + c));
            float2 vb = __half22float2(*(const __half2*)(row + c + 2));
            float v0 = (va.x - mu) * rs * lng[c + 0] + lnb[c + 0];
            float v1 = (va.y - mu) * rs * lng[c + 1] + lnb[c + 1];
            float v2 = (vb.x - mu) * rs * lng[c + 2] + lnb[c + 2];
            float v3 = (vb.y - mu) * rs * lng[c + 3] + lnb[c + 3];
            __half2 h01 = __floats2half2_rn(v0, v1);
            __half2 h23 = __floats2half2_rn(v2, v3);
            *(uint2*)(g_q + obase + c) = make_uint2(*(uint32_t*)&h01, *(uint32_t*)&h23);
        }
    }
}

// ---------------- trilinear gather + fused softmax + weighted sum (t-major) ----------------
__global__ void k_sample() {
    int gw   = (blockIdx.x * blockDim.x + threadIdx.x) >> 5;
    int lane = threadIdx.x & 31;
    if (gw >= MTOT * NHc) return;
    int h = gw % NHc;
    int t = gw / NHc;
    int b = t / Nspat;
    int n = t - b * Nspat;
    int y = n / (Dim * Dim);
    int x = (n / Dim) % Dim;
    int z = n % Dim;

    const float* off = g_off + (size_t)gw * NPc * 3;
    float4 lg = ((const float4*)g_attn)[gw];
    float mx = fmaxf(fmaxf(lg.x, lg.y), fmaxf(lg.z, lg.w));
    float e0 = __expf(lg.x - mx), e1 = __expf(lg.y - mx);
    float e2 = __expf(lg.z - mx), e3 = __expf(lg.w - mx);
    float inv = 1.f / (e0 + e1 + e2 + e3);
    float aw[4] = {e0 * inv, e1 * inv, e2 * inv, e3 * inv};

    const __half* feats = g_feats + ((size_t)(b * NHc + h) * Nspat) * HDc;

    float acc0 = 0.f, acc1 = 0.f;
    #pragma unroll
    for (int p = 0; p < NPc; ++p) {
        float ap = aw[p];
        float ix = fminf(fmaxf((float)y + off[p * 3 + 0], 0.f), (float)(Dim - 1));
        float iy = fminf(fmaxf((float)x + off[p * 3 + 1], 0.f), (float)(Dim - 1));
        float iz = fminf(fmaxf((float)z + off[p * 3 + 2], 0.f), (float)(Dim - 1));
        float x0f = floorf(ix), y0f = floorf(iy), z0f = floorf(iz);
        float fx = ix - x0f, fy = iy - y0f, fz = iz - z0f;
        int x0 = (int)x0f, y0 = (int)y0f, z0 = (int)z0f;
        int x1 = min(x0 + 1, Dim - 1);
        int y1 = min(y0 + 1, Dim - 1);
        int z1 = min(z0 + 1, Dim - 1);
        float wx[2] = {1.f - fx, fx};
        float wy[2] = {1.f - fy, fy};
        float wz[2] = {1.f - fz, fz};
        int   xs[2] = {x0, x1}, ys[2] = {y0, y1}, zs[2] = {z0, z1};
        #pragma unroll
        for (int dz = 0; dz < 2; ++dz)
            #pragma unroll
            for (int dy = 0; dy < 2; ++dy)
                #pragma unroll
                for (int dx = 0; dx < 2; ++dx) {
                    float w = ap * wz[dz] * wy[dy] * wx[dx];
                    const __half2* f = (const __half2*)(feats + (size_t)((zs[dz] * Dim + ys[dy]) * Dim + xs[dx]) * HDc);
                    float2 v = __half22float2(f[lane]);
                    acc0 += w * v.x;
                    acc1 += w * v.y;
                }
    }
    *(__half2*)(g_s + (size_t)t * Cc + h * HDc + lane * 2) = __floats2half2_rn(acc0, acc1);
}

// ---------------- host ----------------
extern "C" void kernel_launch(void* const* d_in, const int* in_sizes, int n_in,
                              void* d_out, int out_size) {
    (void)in_sizes; (void)n_in; (void)out_size;
    const float* f_query = (const float*)d_in[0];
    const float* f_kv    = (const float*)d_in[1];
    const float* ln_g    = (const float*)d_in[2];
    const float* ln_b    = (const float*)d_in[3];
    const float* Wq   = (const float*)d_in[4];
    const float* bq   = (const float*)d_in[5];
    const float* Wo1  = (const float*)d_in[6];
    const float* bo1  = (const float*)d_in[7];
    const float* Wo2  = (const float*)d_in[8];
    const float* bo2  = (const float*)d_in[9];
    const float* Wa   = (const float*)d_in[10];
    const float* ba   = (const float*)d_in[11];
    const float* Wout = (const float*)d_in[12];
    const float* bout = (const float*)d_in[13];
    float* out = (float*)d_out;

    float *p_off, *p_attn, *p_bc;
    cudaGetSymbolAddress((void**)&p_off,  g_off);
    cudaGetSymbolAddress((void**)&p_attn, g_attn);
    cudaGetSymbolAddress((void**)&p_bc,   g_bc);
    __half *q, *hid, *sp, *w1, *wo2, *wo;
    cudaGetSymbolAddress((void**)&q, g_q);
    cudaGetSymbolAddress((void**)&hid, g_hid);
    cudaGetSymbolAddress((void**)&sp, g_s);
    cudaGetSymbolAddress((void**)&w1, g_W1);
    cudaGetSymbolAddress((void**)&wo2, g_Wo2);
    cudaGetSymbolAddress((void**)&wo, g_Wout);

    cudaFuncSetAttribute((const void*)k_sgemm<0,2>, cudaFuncAttributeMaxDynamicSharedMemorySize, NS_SMEM);
    cudaFuncSetAttribute((const void*)k_sgemm_dual, cudaFuncAttributeMaxDynamicSharedMemorySize, NS_SMEM);
    cudaFuncSetAttribute((const void*)k_sgemm<0,1>, cudaFuncAttributeMaxDynamicSharedMemorySize, TR_SMEM);
    cudaFuncSetAttribute(k_lnfuse, cudaFuncAttributeMaxDynamicSharedMemorySize, LN_SMEM);

    // one merged prep launch (weights + bias + KV permute)
    k_prep<<<dim3(16, 16, 48), dim3(32, 8)>>>(Wout, Wo2, Wo1, Wa, Wq, bq, bo1, ba, f_kv);

    // fused stats + transpose + LN -> fp16 q
    k_lnfuse<<<dim3(250, Bc), 256, LN_SMEM>>>(f_query, ln_g, ln_b);

    // hid = relu(q @ W1[0:512] + bc) -> fp16   (500 blocks)
    k_sgemm<0,2><<<dim3(4, 125), 256, NS_SMEM>>>(q, w1, p_bc, nullptr, hid, Cc);
    // off = clip(hid@Wo2+bo2)  AND  attn = q@W1[512:544]+bc[512:]   (250 blocks, one wave)
    k_sgemm_dual<<<dim3(1, 250), 256, NS_SMEM>>>(hid, wo2, bo2, p_off,
                                                 q, w1 + (size_t)512 * 512, p_bc + 512, p_attn);
    // sampling (softmax fused) -> fp16 samp
    k_sample<<<(MTOT * NHc) * 32 / 256, 256>>>();
    // out = samp @ Wout + bout, staged coalesced transposed store
    k_sgemm<0,1><<<dim3(4, 125), 256, TR_SMEM>>>(sp, wo, bout, out, nullptr, Cc);
}

// round 17
// speedup vs baseline: 1.1691x; 1.0769x over previous
#include <cuda_runtime.h>
#include <cuda_bf16.h>
#include <cuda_fp16.h>
#include <cstdint>

#define Bc 2
#define Cc 512
#define NHc 8
#define NPc 4
#define HDc 64
#define Dim 20
#define Nspat 8000          // 20*20*20
#define MTOT (Bc*Nspat)     // 16000
#define LN_EPS 1e-5f

// ---------------- scratch ----------------
__device__ __align__(16) __half g_q   [(size_t)MTOT*Cc];
__device__ __align__(16) __half g_hid [(size_t)MTOT*Cc];
__device__ __align__(16) __half g_s   [(size_t)MTOT*Cc];
__device__ __align__(16) float g_off [(size_t)MTOT*NHc*NPc*3];
__device__ __align__(16) float g_attn[(size_t)MTOT*NHc*NPc];
__device__ __align__(16) __half g_feats[(size_t)Bc*NHc*Nspat*HDc];
__device__ __align__(256) __half g_W1  [640*512];   // folded [Wo1T;WaT]@Wq
__device__ __align__(256) __half g_Wo2 [128*512];
__device__ __align__(256) __half g_Wout[512*512];
__device__ float g_bc[640];

// ================= helpers =================
__device__ __forceinline__ uint32_t smem_u32(const void* p) {
    uint32_t a;
    asm("{ .reg .u64 t; cvta.to.shared.u64 t, %1; cvt.u32.u64 %0, t; }" : "=r"(a) : "l"(p));
    return a;
}
__device__ __forceinline__ void ldsm4(uint32_t* r, uint32_t addr) {
    asm volatile("ldmatrix.sync.aligned.m8n8.x4.shared.b16 {%0,%1,%2,%3}, [%4];"
        : "=r"(r[0]), "=r"(r[1]), "=r"(r[2]), "=r"(r[3]) : "r"(addr));
}
__device__ __forceinline__ void mma_f16(float* c, const uint32_t* a, const uint32_t* b) {
    asm volatile(
        "mma.sync.aligned.m16n8k16.row.col.f32.f16.f16.f32 "
        "{%0,%1,%2,%3}, {%4,%5,%6,%7}, {%8,%9}, {%0,%1,%2,%3};"
        : "+f"(c[0]), "+f"(c[1]), "+f"(c[2]), "+f"(c[3])
        : "r"(a[0]), "r"(a[1]), "r"(a[2]), "r"(a[3]), "r"(b[0]), "r"(b[1]));
}
#define CPA16(dst, src) \
    asm volatile("cp.async.cg.shared.global [%0], [%1], 16;" :: "r"(dst), "l"(src) : "memory")

// ================= fp16 HMMA GEMM (single-A, BK=32, 3-stage, frag prefetch) =================
#define GM_STAGE 20480
#define NS_SMEM (3*GM_STAGE)   // 61440
#define TR_SMEM (128*129*4)    // 66048 for staged transposed epilogue

// omode: 0 = fp32 row-major (+act 2 clip), 1 = fp32 transposed staged, 2 = relu -> fp16
__device__ __forceinline__ void sgemm_body(
    const __half* __restrict__ AH,
    const __half* __restrict__ Bs,
    const float* __restrict__ bias,
    float* __restrict__ Cf, __half* __restrict__ CH,
    int Nc, int act, int omode, int m0, int n0, char* sm)
{
    constexpr int BOFF = 10240;
    const uint32_t smb = smem_u32(sm);
    const int tid = threadIdx.x;
    const int wid = tid >> 5, lane = tid & 31;
    const int wm = wid >> 1;
    const int wn = wid & 1;

    const int tq = lane >> 3, rr = lane & 7;
    const int a_row = rr + (tq & 1) * 8;
    const int a_col = (tq >> 1) * 8;
    const int b_row = rr + (tq >> 1) * 8;
    const int b_col = (tq & 1) * 8;

    const int r2  = tid >> 1;
    const int kc2 = (tid & 1) * 32;

    const __half* AHp = AH + (size_t)(m0 + r2) * 512 + (tid & 1) * 16;
    const __half* Bp  = Bs + (size_t)(n0 + r2) * 512 + (tid & 1) * 16;

    auto ldAB = [&](int buf, int kt) {
        uint32_t ro = smb + buf * GM_STAGE + r2 * 80 + kc2;
        const int go = kt * 32;
        CPA16(ro,             AHp + go);
        CPA16(ro + 16,        AHp + go + 8);
        CPA16(ro + BOFF,      Bp + go);
        CPA16(ro + BOFF + 16, Bp + go + 8);
        asm volatile("cp.async.commit_group;" ::: "memory");
    };

    float acc[2][8][4];
    #pragma unroll
    for (int mi = 0; mi < 2; ++mi)
        #pragma unroll
        for (int j = 0; j < 8; ++j)
            #pragma unroll
            for (int q = 0; q < 4; ++q) acc[mi][j][q] = 0.f;

    ldAB(0, 0);
    ldAB(1, 1);

    uint32_t ah[2][2][4], bf[2][4][4];
    int buf = 0;
    for (int kt = 0; kt < 16; ++kt) {
        if (kt + 2 < 16) {
            ldAB((buf + 2) % 3, kt + 2);
            asm volatile("cp.async.wait_group 2;" ::: "memory");
        } else if (kt + 1 < 16) {
            asm volatile("cp.async.wait_group 1;" ::: "memory");
        } else {
            asm volatile("cp.async.wait_group 0;" ::: "memory");
        }
        __syncthreads();
        uint32_t abase = smb + buf * GM_STAGE;
        uint32_t bbase = abase + BOFF;
        auto ldfr = [&](int s, int kc) {
            #pragma unroll
            for (int mi = 0; mi < 2; ++mi) {
                uint32_t ad = abase + (uint32_t)(wm * 32 + mi * 16 + a_row) * 80 + (kc + a_col) * 2;
                ldsm4(ah[s][mi], ad);
            }
            #pragma unroll
            for (int p = 0; p < 4; ++p) {
                uint32_t bd = bbase + (uint32_t)(wn * 64 + p * 16 + b_row) * 80 + (kc + b_col) * 2;
                ldsm4(bf[s][p], bd);
            }
        };
        ldfr(0, 0);
        #pragma unroll
        for (int ks = 0; ks < 2; ++ks) {
            if (ks == 0) ldfr(1, 16);
            #pragma unroll
            for (int mi = 0; mi < 2; ++mi)
                #pragma unroll
                for (int j = 0; j < 8; ++j)
                    mma_f16(acc[mi][j], ah[ks][mi], &bf[ks][j >> 1][(j & 1) * 2]);
        }
        __syncthreads();
        buf = (buf + 1) % 3;
    }

    if (omode == 1) {
        float* smf = (float*)sm;   // [128][129]
        #pragma unroll
        for (int mi = 0; mi < 2; ++mi) {
            #pragma unroll
            for (int j = 0; j < 8; ++j) {
                int c0 = wn * 64 + j * 8 + (lane & 3) * 2;
                float b0 = bias[n0 + c0], b1 = bias[n0 + c0 + 1];
                #pragma unroll
                for (int half = 0; half < 2; ++half) {
                    int r = wm * 32 + mi * 16 + (lane >> 2) + half * 8;
                    smf[r * 129 + c0]     = acc[mi][j][half * 2 + 0] + b0;
                    smf[r * 129 + c0 + 1] = acc[mi][j][half * 2 + 1] + b1;
                }
            }
        }
        __syncthreads();
        #pragma unroll 4
        for (int i = 0; i < 64; ++i) {
            int idx = i * 256 + tid;
            int cl = idx >> 7, rl = idx & 127;
            int row = m0 + rl;
            int b = row / Nspat, n = row - b * Nspat;
            Cf[((size_t)(b * Cc + n0 + cl)) * Nspat + n] = smf[rl * 129 + cl];
        }
        return;
    }

    #pragma unroll
    for (int mi = 0; mi < 2; ++mi) {
        int row0 = m0 + wm * 32 + mi * 16 + (lane >> 2);
        #pragma unroll
        for (int j = 0; j < 8; ++j) {
            int col0 = n0 + wn * 64 + j * 8 + (lane & 3) * 2;
            if (col0 >= Nc) continue;
            float b0 = bias[col0], b1 = bias[col0 + 1];
            #pragma unroll
            for (int half = 0; half < 2; ++half) {
                int row = row0 + half * 8;
                float v0 = acc[mi][j][half * 2 + 0] + b0;
                float v1 = acc[mi][j][half * 2 + 1] + b1;
                if (omode == 2) {
                    v0 = fmaxf(v0, 0.f); v1 = fmaxf(v1, 0.f);
                    *(__half2*)(CH + (size_t)row * Nc + col0) = __floats2half2_rn(v0, v1);
                } else {
                    if (act == 2) {
                        v0 = fminf(fmaxf(v0, -3.f), 3.f);
                        v1 = fminf(fmaxf(v1, -3.f), 3.f);
                    }
                    *(float2*)(Cf + (size_t)row * Nc + col0) = make_float2(v0, v1);
                }
            }
        }
    }
}

template<int ACT, int OMODE>
__global__ void __launch_bounds__(256, 2) k_sgemm(
    const __half* __restrict__ AH,
    const __half* __restrict__ Bs,
    const float* __restrict__ bias,
    float* __restrict__ Cf, __half* __restrict__ CH,
    int Nc)
{
    extern __shared__ __align__(1024) char sm_dyn[];
    sgemm_body(AH, Bs, bias, Cf, CH, Nc, ACT, OMODE,
               blockIdx.y * 128, blockIdx.x * 128, sm_dyn);
}

// dual: blocks [0,125) -> off = clip(hid@Wo2+bo2); [125,250) -> attn = q@W1[512:]+bc[512:]
__global__ void __launch_bounds__(256, 2) k_sgemm_dual(
    const __half* __restrict__ hid, const __half* __restrict__ wo2, const float* __restrict__ bo2,
    float* __restrict__ off,
    const __half* __restrict__ q, const __half* __restrict__ w1a, const float* __restrict__ bca,
    float* __restrict__ attn)
{
    extern __shared__ __align__(1024) char sm_dyn[];
    int by = blockIdx.y;
    if (by < 125)
        sgemm_body(hid, wo2, bo2, off, nullptr, NHc * NPc * 3, 2, 0, by * 128, 0, sm_dyn);
    else
        sgemm_body(q, w1a, bca, attn, nullptr, NHc * NPc, 0, 0, (by - 125) * 128, 0, sm_dyn);
}

// ---------------- merged prep + KV permute + LN ----------------
// grid (16,16,50), block (32,8) = 256 thr, dynamic smem LN_SMEM:
//   z==0 -> Wout transpose; z==1 -> Wo2 transpose
//   z in [2,22) -> wfold row-group n0=(z-2)*32, j0=bx*32 (by==0 only)
//   z==22 -> bias (by==0, bx<3)
//   z in [23,48) -> KV permute, blk = (z-23)*256 + by*16 + bx
//   z in [48,50) -> LN: batch b=z-48, token group idx=by*16+bx (<250)
#define LN_SMEM (32*514*2 + 2*8*32*4 + 64*4)
__global__ void __launch_bounds__(256) k_prep(
    const float* __restrict__ Wout, const float* __restrict__ Wo2,
    const float* __restrict__ Wo1,  const float* __restrict__ Wa,
    const float* __restrict__ Wq,
    const float* __restrict__ bq,   const float* __restrict__ bo1,
    const float* __restrict__ ba,
    const float* __restrict__ fkv,
    const float* __restrict__ fq,
    const float* __restrict__ lng,  const float* __restrict__ lnb)
{
    extern __shared__ __align__(16) char sm_dyn[];
    int z = blockIdx.z;
    int tx = threadIdx.x, ty = threadIdx.y;
    int tid = ty * 32 + tx;
    if (z >= 48) {
        // ---- LN branch ----
        int idx = blockIdx.y * 16 + blockIdx.x;
        if (idx >= 250) return;
        __half* tile = (__half*)sm_dyn;                   // [32][514]
        float* sredS  = (float*)(sm_dyn + 32 * 514 * 2);
        float* sredSS = sredS + 8 * 32;
        float* smean  = sredSS + 8 * 32;
        float* srstd  = smean + 32;
        int b  = z - 48;
        int n0 = idx * 32;
        int warp = ty, lane = tx;
        const float* src = fq + (size_t)b * Cc * Nspat + n0 + lane;
        float s = 0.f, ss = 0.f;
        #pragma unroll 8
        for (int it = 0; it < 64; ++it) {
            int c = it * 8 + warp;
            float v = src[(size_t)c * Nspat];
            s += v; ss += v * v;
            tile[lane * 514 + c] = __float2half_rn(v);
        }
        sredS[warp * 32 + lane] = s;
        sredSS[warp * 32 + lane] = ss;
        __syncthreads();
        if (warp == 0) {
            float st = 0.f, sst = 0.f;
            #pragma unroll
            for (int w = 0; w < 8; ++w) {
                st  += sredS[w * 32 + lane];
                sst += sredSS[w * 32 + lane];
            }
            float mu = st * (1.f / Cc);
            float var = sst * (1.f / Cc) - mu * mu;
            smean[lane] = mu;
            srstd[lane] = rsqrtf(var + LN_EPS);
        }
        __syncthreads();
        #pragma unroll
        for (int i = 0; i < 4; ++i) {
            int tok = warp * 4 + i;
            float mu = smean[tok], rs = srstd[tok];
            size_t obase = (size_t)(b * Nspat + n0 + tok) * Cc;
            const __half* row = tile + tok * 514;
            #pragma unroll
            for (int k = 0; k < 4; ++k) {
                int c = lane * 4 + k * 128;
                float2 va = __half22float2(*(const __half2*)(row + c));
                float2 vb = __half22float2(*(const __half2*)(row + c + 2));
                float v0 = (va.x - mu) * rs * lng[c + 0] + lnb[c + 0];
                float v1 = (va.y - mu) * rs * lng[c + 1] + lnb[c + 1];
                float v2 = (vb.x - mu) * rs * lng[c + 2] + lnb[c + 2];
                float v3 = (vb.y - mu) * rs * lng[c + 3] + lnb[c + 3];
                __half2 h01 = __floats2half2_rn(v0, v1);
                __half2 h23 = __floats2half2_rn(v2, v3);
                *(uint2*)(g_q + obase + c) = make_uint2(*(uint32_t*)&h01, *(uint32_t*)&h23);
            }
        }
        return;
    }
    if (z >= 23) {
        // ---- KV permute ----
        float* PS = (float*)sm_dyn;   // HDc*21 floats
        int blk = (z - 23) * 256 + blockIdx.y * 16 + blockIdx.x;
        int x = blk % Dim;
        int y = (blk / Dim) % Dim;
        int h = (blk / (Dim * Dim)) % NHc;
        int b = blk / (Dim * Dim * NHc);
        const float* src = fkv + ((size_t)(b * Cc + h * HDc)) * Nspat + (y * Dim + x) * Dim;
        for (int idx = tid; idx < HDc * Dim; idx += 256) {
            int hd = idx / Dim, zz = idx - hd * Dim;
            PS[hd * 21 + zz] = src[(size_t)hd * Nspat + zz];
        }
        __syncthreads();
        __half* dst = g_feats + ((size_t)(b * NHc + h) * Nspat) * HDc;
        for (int idx = tid; idx < HDc * Dim; idx += 256) {
            int zz = idx / HDc, hd = idx - zz * HDc;
            dst[(size_t)((zz * Dim + y) * Dim + x) * HDc + hd] = __float2half_rn(PS[hd * 21 + zz]);
        }
        return;
    }
    float (*T1)[33] = (float(*)[33])sm_dyn;
    float (*T2)[33] = (float(*)[33])(sm_dyn + 32 * 33 * 4);
    if (z < 2) {
        const float* W = (z == 0) ? Wout : Wo2;
        __half* Hd = (z == 0) ? g_Wout : g_Wo2;
        int Ncols = (z == 0) ? 512 : NHc * NPc * 3;
        int Npad  = (z == 0) ? 512 : 128;
        int k0 = blockIdx.y * 32, n0 = blockIdx.x * 32;
        if (n0 >= Npad) return;
        #pragma unroll
        for (int i = 0; i < 32; i += 8) {
            int k = k0 + ty + i, n = n0 + tx;
            T1[ty + i][tx] = (n < Ncols) ? W[(size_t)k * Ncols + n] : 0.f;
        }
        __syncthreads();
        #pragma unroll
        for (int i = 0; i < 32; i += 8) {
            int n = n0 + ty + i, k = k0 + tx;
            Hd[(size_t)n * 512 + k] = __float2half_rn(T1[tx][ty + i]);
        }
        return;
    }
    if (z < 22) {
        if (blockIdx.y != 0) return;
        int n0 = (z - 2) * 32, j0 = blockIdx.x * 32;
        float acc[4] = {0.f, 0.f, 0.f, 0.f};
        for (int k0 = 0; k0 < 512; k0 += 32) {
            #pragma unroll
            for (int i = 0; i < 32; i += 8) {
                int k = k0 + ty + i, n = n0 + tx;
                float v = 0.f;
                if (n < 512)      v = Wo1[(size_t)k * 512 + n];
                else if (n < 544) v = Wa[(size_t)k * 32 + (n - 512)];
                T1[ty + i][tx] = v;
                T2[ty + i][tx] = Wq[(size_t)(j0 + ty + i) * 512 + k0 + tx];
            }
            __syncthreads();
            #pragma unroll 8
            for (int k = 0; k < 32; ++k) {
                float t1 = T1[k][tx];
                #pragma unroll
                for (int r = 0; r < 4; ++r) acc[r] += t1 * T2[ty + 8 * r][k];
            }
            __syncthreads();
        }
        #pragma unroll
        for (int r = 0; r < 4; ++r)
            g_W1[(size_t)(n0 + tx) * 512 + j0 + ty + 8 * r] = __float2half_rn(acc[r]);
        return;
    }
    // z == 22: bias
    if (blockIdx.y != 0 || blockIdx.x >= 3) return;
    int n = blockIdx.x * 256 + tid;
    if (n >= 640) return;
    float s = 0.f;
    if (n < 512) {
        s = bo1[n];
        for (int j = 0; j < 512; ++j) s += bq[j] * Wo1[(size_t)j * 512 + n];
    } else if (n < 544) {
        int c = n - 512;
        s = ba[c];
        for (int j = 0; j < 512; ++j) s += bq[j] * Wa[(size_t)j * 32 + c];
    }
    g_bc[n] = s;
}

// ---------------- trilinear gather + fused softmax + weighted sum (t-major) ----------------
__global__ void k_sample() {
    int gw   = (blockIdx.x * blockDim.x + threadIdx.x) >> 5;
    int lane = threadIdx.x & 31;
    if (gw >= MTOT * NHc) return;
    int h = gw % NHc;
    int t = gw / NHc;
    int b = t / Nspat;
    int n = t - b * Nspat;
    int y = n / (Dim * Dim);
    int x = (n / Dim) % Dim;
    int z = n % Dim;

    const float* off = g_off + (size_t)gw * NPc * 3;
    float4 lg = ((const float4*)g_attn)[gw];
    float mx = fmaxf(fmaxf(lg.x, lg.y), fmaxf(lg.z, lg.w));
    float e0 = __expf(lg.x - mx), e1 = __expf(lg.y - mx);
    float e2 = __expf(lg.z - mx), e3 = __expf(lg.w - mx);
    float inv = 1.f / (e0 + e1 + e2 + e3);
    float aw[4] = {e0 * inv, e1 * inv, e2 * inv, e3 * inv};

    const __half* feats = g_feats + ((size_t)(b * NHc + h) * Nspat) * HDc;

    float acc0 = 0.f, acc1 = 0.f;
    #pragma unroll
    for (int p = 0; p < NPc; ++p) {
        float ap = aw[p];
        float ix = fminf(fmaxf((float)y + off[p * 3 + 0], 0.f), (float)(Dim - 1));
        float iy = fminf(fmaxf((float)x + off[p * 3 + 1], 0.f), (float)(Dim - 1));
        float iz = fminf(fmaxf((float)z + off[p * 3 + 2], 0.f), (float)(Dim - 1));
        float x0f = floorf(ix), y0f = floorf(iy), z0f = floorf(iz);
        float fx = ix - x0f, fy = iy - y0f, fz = iz - z0f;
        int x0 = (int)x0f, y0 = (int)y0f, z0 = (int)z0f;
        int x1 = min(x0 + 1, Dim - 1);
        int y1 = min(y0 + 1, Dim - 1);
        int z1 = min(z0 + 1, Dim - 1);
        float wx[2] = {1.f - fx, fx};
        float wy[2] = {1.f - fy, fy};
        float wz[2] = {1.f - fz, fz};
        int   xs[2] = {x0, x1}, ys[2] = {y0, y1}, zs[2] = {z0, z1};
        #pragma unroll
        for (int dz = 0; dz < 2; ++dz)
            #pragma unroll
            for (int dy = 0; dy < 2; ++dy)
                #pragma unroll
                for (int dx = 0; dx < 2; ++dx) {
                    float w = ap * wz[dz] * wy[dy] * wx[dx];
                    const __half2* f = (const __half2*)(feats + (size_t)((zs[dz] * Dim + ys[dy]) * Dim + xs[dx]) * HDc);
                    float2 v = __half22float2(f[lane]);
                    acc0 += w * v.x;
                    acc1 += w * v.y;
                }
    }
    *(__half2*)(g_s + (size_t)t * Cc + h * HDc + lane * 2) = __floats2half2_rn(acc0, acc1);
}

// ---------------- host ----------------
extern "C" void kernel_launch(void* const* d_in, const int* in_sizes, int n_in,
                              void* d_out, int out_size) {
    (void)in_sizes; (void)n_in; (void)out_size;
    const float* f_query = (const float*)d_in[0];
    const float* f_kv    = (const float*)d_in[1];
    const float* ln_g    = (const float*)d_in[2];
    const float* ln_b    = (const float*)d_in[3];
    const float* Wq   = (const float*)d_in[4];
    const float* bq   = (const float*)d_in[5];
    const float* Wo1  = (const float*)d_in[6];
    const float* bo1  = (const float*)d_in[7];
    const float* Wo2  = (const float*)d_in[8];
    const float* bo2  = (const float*)d_in[9];
    const float* Wa   = (const float*)d_in[10];
    const float* ba   = (const float*)d_in[11];
    const float* Wout = (const float*)d_in[12];
    const float* bout = (const float*)d_in[13];
    float* out = (float*)d_out;

    float *p_off, *p_attn, *p_bc;
    cudaGetSymbolAddress((void**)&p_off,  g_off);
    cudaGetSymbolAddress((void**)&p_attn, g_attn);
    cudaGetSymbolAddress((void**)&p_bc,   g_bc);
    __half *q, *hid, *sp, *w1, *wo2, *wo;
    cudaGetSymbolAddress((void**)&q, g_q);
    cudaGetSymbolAddress((void**)&hid, g_hid);
    cudaGetSymbolAddress((void**)&sp, g_s);
    cudaGetSymbolAddress((void**)&w1, g_W1);
    cudaGetSymbolAddress((void**)&wo2, g_Wo2);
    cudaGetSymbolAddress((void**)&wo, g_Wout);

    cudaFuncSetAttribute((const void*)k_sgemm<0,2>, cudaFuncAttributeMaxDynamicSharedMemorySize, NS_SMEM);
    cudaFuncSetAttribute((const void*)k_sgemm_dual, cudaFuncAttributeMaxDynamicSharedMemorySize, NS_SMEM);
    cudaFuncSetAttribute((const void*)k_sgemm<0,1>, cudaFuncAttributeMaxDynamicSharedMemorySize, TR_SMEM);
    cudaFuncSetAttribute(k_prep, cudaFuncAttributeMaxDynamicSharedMemorySize, LN_SMEM);

    // one merged prep launch (weights + bias + KV permute + layernorm)
    k_prep<<<dim3(16, 16, 50), dim3(32, 8), LN_SMEM>>>(
        Wout, Wo2, Wo1, Wa, Wq, bq, bo1, ba, f_kv, f_query, ln_g, ln_b);

    // hid = relu(q @ W1[0:512] + bc) -> fp16   (500 blocks)
    k_sgemm<0,2><<<dim3(4, 125), 256, NS_SMEM>>>(q, w1, p_bc, nullptr, hid, Cc);
    // off = clip(hid@Wo2+bo2)  AND  attn = q@W1[512:544]+bc[512:]   (250 blocks, one wave)
    k_sgemm_dual<<<dim3(1, 250), 256, NS_SMEM>>>(hid, wo2, bo2, p_off,
                                                 q, w1 + (size_t)512 * 512, p_bc + 512, p_attn);
    // sampling (softmax fused) -> fp16 samp
    k_sample<<<(MTOT * NHc) * 32 / 256, 256>>>();
    // out = samp @ Wout + bout, staged coalesced transposed store
    k_sgemm<0,1><<<dim3(4, 125), 256, TR_SMEM>>>(sp, wo, bout, out, nullptr, Cc);
}